// round 7
// baseline (speedup 1.0000x reference)
#include <cuda_runtime.h>
#include <cuda_bf16.h>

// Problem: F=128 features, N=8192 batch, D=128 d_model.
// out[f,n,d] = LayerNorm_d( x[n,f]*W[f,d] + b[f,d] ) * gamma[d] + beta[d]
//
// Algebraic fusion: for fixed f the embedding row is affine in scalar x, so
//   mean      = x*meanW[f] + meanb[f]
//   centered  = x*Wc[f,d] + bc[f,d]           (Wc=W-meanW, bc=b-meanb)
//   var       = A[f]*x^2 + 2*B[f]*x + C[f]    (A=mean Wc^2, B=mean Wc*bc, C=mean bc^2)
// => no per-row reduction at runtime; kernel is pure elementwise + STG.128.

#define F_DIM 128
#define D_DIM 128
#define N_BATCH 8192
#define EPS 1e-5f

// Scratch (allocation-free rule: __device__ globals)
__device__ float g_Wg[F_DIM * D_DIM];   // (W - meanW) * gamma
__device__ float g_bg[F_DIM * D_DIM];   // (b - meanb) * gamma
__device__ float g_A[F_DIM];
__device__ float g_B[F_DIM];
__device__ float g_C[F_DIM];

__device__ __forceinline__ float block_sum_128(float v, float* s, int tid) {
    #pragma unroll
    for (int o = 16; o > 0; o >>= 1) v += __shfl_xor_sync(0xffffffffu, v, o);
    if ((tid & 31) == 0) s[tid >> 5] = v;
    __syncthreads();
    v = s[0] + s[1] + s[2] + s[3];
    __syncthreads();  // protect s reuse
    return v;
}

// One block per feature, 128 threads (one per d).
__global__ void precompute_kernel(const float* __restrict__ W,
                                  const float* __restrict__ b,
                                  const float* __restrict__ gamma) {
    __shared__ float s[4];
    const int f = blockIdx.x;
    const int d = threadIdx.x;

    const float w  = W[f * D_DIM + d];
    const float bb = b[f * D_DIM + d];

    const float meanW = block_sum_128(w,  s, d) * (1.0f / D_DIM);
    const float meanB = block_sum_128(bb, s, d) * (1.0f / D_DIM);

    const float wc = w  - meanW;
    const float bc = bb - meanB;

    const float A = block_sum_128(wc * wc, s, d) * (1.0f / D_DIM);
    const float B = block_sum_128(wc * bc, s, d) * (1.0f / D_DIM);
    const float C = block_sum_128(bc * bc, s, d) * (1.0f / D_DIM);

    const float g = gamma[d];
    g_Wg[f * D_DIM + d] = wc * g;
    g_bg[f * D_DIM + d] = bc * g;
    if (d == 0) { g_A[f] = A; g_B[f] = B; g_C[f] = C; }
}

// Main kernel: block = (feature f, n-chunk). 8 warps/block; one warp per row;
// lane l covers d in [4l, 4l+4) via float4 -> coalesced 512B stores per warp.
__global__ void __launch_bounds__(256)
embed_ln_kernel(const float* __restrict__ x,
                const float* __restrict__ beta,
                float* __restrict__ out) {
    const int f    = blockIdx.x;
    const int lane = threadIdx.x & 31;
    const int warp = threadIdx.x >> 5;

    // Per-lane constants for this feature (hoisted out of the n loop)
    const float4 wg = reinterpret_cast<const float4*>(g_Wg + f * D_DIM)[lane];
    const float4 bg = reinterpret_cast<const float4*>(g_bg + f * D_DIM)[lane];
    const float4 bt = reinterpret_cast<const float4*>(beta)[lane];
    const float  A  = g_A[f];
    const float  B2 = 2.0f * g_B[f];
    const float  C  = g_C[f];

    float4* __restrict__ outf =
        reinterpret_cast<float4*>(out + (size_t)f * N_BATCH * D_DIM);
    const int row_stride = gridDim.y * 8;

    for (int n = blockIdx.y * 8 + warp; n < N_BATCH; n += row_stride) {
        const float xv = __ldg(x + (size_t)n * F_DIM + f);   // uniform across warp
        // var = A*x^2 + 2B*x + C  (>=0 mathematically; clamp rounding)
        const float var  = fmaf(fmaf(A, xv, B2), xv, C);
        const float rinv = rsqrtf(fmaxf(var, 0.0f) + EPS);

        float4 o;
        o.x = fmaf(rinv, fmaf(xv, wg.x, bg.x), bt.x);
        o.y = fmaf(rinv, fmaf(xv, wg.y, bg.y), bt.y);
        o.z = fmaf(rinv, fmaf(xv, wg.z, bg.z), bt.z);
        o.w = fmaf(rinv, fmaf(xv, wg.w, bg.w), bt.w);

        outf[(size_t)n * (D_DIM / 4) + lane] = o;
    }
}

extern "C" void kernel_launch(void* const* d_in, const int* in_sizes, int n_in,
                              void* d_out, int out_size) {
    const float* x     = (const float*)d_in[0];  // [8192, 128]
    const float* W     = (const float*)d_in[1];  // [128, 128]
    const float* b     = (const float*)d_in[2];  // [128, 128]
    const float* gamma = (const float*)d_in[3];  // [128]
    const float* beta  = (const float*)d_in[4];  // [128]
    float* out = (float*)d_out;                  // [128, 8192, 128]

    precompute_kernel<<<F_DIM, D_DIM>>>(W, b, gamma);

    dim3 grid(F_DIM, 64);   // 8192 blocks; 16 rows per warp
    embed_ln_kernel<<<grid, 256>>>(x, beta, out);
}